// round 3
// baseline (speedup 1.0000x reference)
#include <cuda_runtime.h>
#include <cuda_fp16.h>
#include <cstdint>

#define NB 4096   // tokens
#define NH 1024   // hidden
#define ND 4096   // expert dim
#define NE 8      // experts

// ---------------- scratch (__device__ globals: allocation-guard safe) ----------------
__device__ __half g_xh [(size_t)NB * NH];          //  8 MB  x fp16
__device__ __half g_w1h[(size_t)NE * NH * ND];     // 64 MB  w1 fp16 [e][h][d]
__device__ __half g_w2h[(size_t)NE * ND * NH];     // 64 MB  w2 fp16 [e][d][h]
__device__ __half g_h  [(size_t)NE * NB * ND];     // 256 MB h scratch
__device__ int    g_cnt[NE];
__device__ int    g_idx[NE * NB];
__device__ float  g_scale[NE * NB];
__device__ float  g_psum[NE];
__device__ float  g_rsum[NE];

// ---------------- helpers ----------------
__device__ __forceinline__ uint32_t smem_u32(const void* p) {
    return (uint32_t)__cvta_generic_to_shared(p);
}
__device__ __forceinline__ void cp16(uint32_t smem, const void* gmem) {
    asm volatile("cp.async.cg.shared.global [%0], [%1], 16;\n"
                 :: "r"(smem), "l"(gmem) : "memory");
}

// ---------------- init ----------------
__global__ void init_kernel(float* __restrict__ y) {
    size_t i = (size_t)blockIdx.x * blockDim.x + threadIdx.x;
    if (i < (size_t)NB * NH) y[i] = 0.f;
    if (i < NE) { g_cnt[i] = 0; g_psum[i] = 0.f; g_rsum[i] = 0.f; }
}

// ---------------- fp32 -> fp16 ----------------
template<int WHICH>
__global__ void f2h_kernel(const float* __restrict__ src, size_t n4) {
    size_t i = (size_t)blockIdx.x * blockDim.x + threadIdx.x;
    if (i >= n4) return;
    __half* dst = (WHICH == 0) ? g_xh : (WHICH == 1) ? g_w1h : g_w2h;
    float4 v = reinterpret_cast<const float4*>(src)[i];
    __half2* d2 = reinterpret_cast<__half2*>(dst) + i * 2;
    d2[0] = __floats2half2_rn(v.x, v.y);
    d2[1] = __floats2half2_rn(v.z, v.w);
}

// ---------------- gating ----------------
__global__ void gate_kernel(const float* __restrict__ x,
                            const float* __restrict__ gw,
                            const float* __restrict__ gb) {
    __shared__ float sx[NH];
    __shared__ float slog[NE];
    const int b = blockIdx.x, tid = threadIdx.x;
    for (int i = tid; i < NH; i += 256) sx[i] = x[(size_t)b * NH + i];
    __syncthreads();
    const int w = tid >> 5, lane = tid & 31;
    float s = 0.f;
    for (int i = lane; i < NH; i += 32) s += sx[i] * gw[i * NE + w];
    #pragma unroll
    for (int o = 16; o; o >>= 1) s += __shfl_xor_sync(0xffffffffu, s, o);
    if (lane == 0) slog[w] = s + gb[w];
    __syncthreads();
    if (tid == 0) {
        float p[NE];
        float mx = slog[0];
        #pragma unroll
        for (int e = 1; e < NE; e++) mx = fmaxf(mx, slog[e]);
        float den = 0.f;
        #pragma unroll
        for (int e = 0; e < NE; e++) { p[e] = expf(slog[e] - mx); den += p[e]; }
        float inv = 1.f / den;
        #pragma unroll
        for (int e = 0; e < NE; e++) p[e] *= inv;
        int e1 = 0; float p1 = p[0];
        #pragma unroll
        for (int e = 1; e < NE; e++) if (p[e] > p1) { p1 = p[e]; e1 = e; }
        int e2 = (e1 == 0) ? 1 : 0; float p2 = p[e2];
        #pragma unroll
        for (int e = 0; e < NE; e++)
            if (e != e1 && p[e] > p2) { p2 = p[e]; e2 = e; }
        int pos = atomicAdd(&g_cnt[e1], 1);
        g_idx[e1 * NB + pos] = b; g_scale[e1 * NB + pos] = p1 * 0.5f;
        pos = atomicAdd(&g_cnt[e2], 1);
        g_idx[e2 * NB + pos] = b; g_scale[e2 * NB + pos] = p2 * 0.5f;
        #pragma unroll
        for (int e = 0; e < NE; e++) atomicAdd(&g_psum[e], p[e]);
        atomicAdd(&g_rsum[e1], 1.f);
        atomicAdd(&g_rsum[e2], 1.f);
    }
}

// ---------------- grouped GEMM: CTA tile 128x256, warp tile 64x64, 4-stage cp.async ----------------
// smem: A stages 4 x [128][40] halves (10240B each), B stages 4 x [32][264] halves (16896B each)
// ISB==false: h = relu(Xg @ W1 + b1)    (KLEN=NH, NDIM=ND, NSPLIT=1)
// ISB==true : y += scale*(h @ W2 + b2)  (KLEN=ND/2, NDIM=NH, NSPLIT=2, atomic, bias on split 0)
template<int KLEN, int NDIM, bool ISB, int NSPLIT>
__global__ void __launch_bounds__(256)
moe_gemm(const float* __restrict__ bias, float* __restrict__ y) {
    constexpr int KT = KLEN / 32;
    const int zi    = blockIdx.z;
    const int e     = (NSPLIT == 1) ? zi : (zi >> 1);
    const int split = (NSPLIT == 1) ? 0  : (zi & 1);
    const int cnt = g_cnt[e];
    const int m0  = blockIdx.y * 128;
    if (m0 >= cnt) return;
    const int n0    = blockIdx.x * 256;
    const int kbase = split * KLEN;
    const int tid   = threadIdx.x;

    extern __shared__ __align__(1024) char smem[];
    const uint32_t sA = smem_u32(smem);            // 4 * 10240
    const uint32_t sB = sA + 4 * 10240;            // 4 * 16896

    // ---- gmem source pointers ----
    const int ar = tid >> 1;                        // A row this thread loads
    const __half* Arow;
    if (ISB) {
        Arow = g_h + ((size_t)e * NB + m0 + ar) * ND + kbase;
    } else {
        const int s0  = m0 + ar;
        const int tok = g_idx[e * NB + (s0 < cnt ? s0 : 0)];
        Arow = g_xh + (size_t)tok * NH;
    }
    const __half* W = (ISB ? g_w2h : g_w1h)
                    + (size_t)e * (size_t)(KLEN * NSPLIT) * NDIM
                    + (size_t)kbase * NDIM + n0;
    const int br = tid >> 3;                        // B row this thread loads

    auto load_stage = [&](int chunk, int s) {
        const uint32_t as = sA + s * 10240 + ar * 80;
        const __half* ag = Arow + chunk * 32;
        #pragma unroll
        for (int j = 0; j < 2; j++) {
            const int c4 = (tid & 1) * 2 + j;       // 0..3
            cp16(as + c4 * 16, ag + c4 * 8);
        }
        const uint32_t bs = sB + s * 16896 + br * 528;
        const __half* bg = W + (size_t)(chunk * 32 + br) * NDIM;
        #pragma unroll
        for (int j = 0; j < 4; j++) {
            const int cc = (tid & 7) * 4 + j;       // 0..31
            cp16(bs + cc * 16, bg + cc * 8);
        }
        asm volatile("cp.async.commit_group;" ::: "memory");
    };

    float acc[4][8][4];
    #pragma unroll
    for (int i = 0; i < 4; i++)
        #pragma unroll
        for (int j = 0; j < 8; j++)
            #pragma unroll
            for (int q = 0; q < 4; q++) acc[i][j][q] = 0.f;

    const int lane = tid & 31, warp = tid >> 5;
    const int wm = (warp >> 2) * 64, wn = (warp & 3) * 64;
    const uint32_t aoff = (uint32_t)(wm + (lane & 15)) * 80 + (lane >> 4) * 16;
    const uint32_t boff = (uint32_t)(lane & 15) * 528 + (uint32_t)(wn + (lane >> 4) * 8) * 2;

    load_stage(0, 0);
    load_stage(1, 1);
    load_stage(2, 2);

    for (int i = 0; i < KT; i++) {
        if (i < KT - 2)       asm volatile("cp.async.wait_group 2;" ::: "memory");
        else if (i == KT - 2) asm volatile("cp.async.wait_group 1;" ::: "memory");
        else                  asm volatile("cp.async.wait_group 0;" ::: "memory");
        __syncthreads();
        if (i + 3 < KT) load_stage(i + 3, (i + 3) & 3);

        const int s = i & 3;
        const uint32_t ab = sA + s * 10240 + aoff;
        const uint32_t bb = sB + s * 16896 + boff;
        #pragma unroll
        for (int ks = 0; ks < 2; ks++) {
            uint32_t a[4][4], b[4][4];
            #pragma unroll
            for (int im = 0; im < 4; im++) {
                asm volatile("ldmatrix.sync.aligned.m8n8.x4.shared.b16 {%0,%1,%2,%3}, [%4];"
                             : "=r"(a[im][0]), "=r"(a[im][1]), "=r"(a[im][2]), "=r"(a[im][3])
                             : "r"(ab + im * 16 * 80 + ks * 32));
            }
            #pragma unroll
            for (int g = 0; g < 4; g++) {
                asm volatile("ldmatrix.sync.aligned.m8n8.x4.trans.shared.b16 {%0,%1,%2,%3}, [%4];"
                             : "=r"(b[g][0]), "=r"(b[g][1]), "=r"(b[g][2]), "=r"(b[g][3])
                             : "r"(bb + ks * 16 * 528 + g * 32));
            }
            #pragma unroll
            for (int im = 0; im < 4; im++)
                #pragma unroll
                for (int jn = 0; jn < 8; jn++) {
                    const uint32_t b0 = b[jn >> 1][(jn & 1) * 2 + 0];
                    const uint32_t b1 = b[jn >> 1][(jn & 1) * 2 + 1];
                    asm volatile("mma.sync.aligned.m16n8k16.row.col.f32.f16.f16.f32 "
                                 "{%0,%1,%2,%3},{%4,%5,%6,%7},{%8,%9},{%0,%1,%2,%3};"
                                 : "+f"(acc[im][jn][0]), "+f"(acc[im][jn][1]),
                                   "+f"(acc[im][jn][2]), "+f"(acc[im][jn][3])
                                 : "r"(a[im][0]), "r"(a[im][1]), "r"(a[im][2]), "r"(a[im][3]),
                                   "r"(b0), "r"(b1));
                }
        }
    }

    // ---- epilogue ----
    const int rb = lane >> 2;
    const int cb = (lane & 3) * 2;
    float bcol[16];
    #pragma unroll
    for (int jn = 0; jn < 8; jn++) {
        const int gc = n0 + wn + jn * 8 + cb;
        if (ISB && split != 0) { bcol[jn * 2] = 0.f; bcol[jn * 2 + 1] = 0.f; }
        else { bcol[jn * 2] = bias[e * NDIM + gc]; bcol[jn * 2 + 1] = bias[e * NDIM + gc + 1]; }
    }
    #pragma unroll
    for (int im = 0; im < 4; im++) {
        #pragma unroll
        for (int h = 0; h < 2; h++) {
            const int row  = wm + im * 16 + rb + h * 8;
            const int slot = m0 + row;
            if (slot >= cnt) continue;
            if (!ISB) {
                __half* drow = &g_h[((size_t)e * NB + slot) * ND + n0 + wn];
                #pragma unroll
                for (int jn = 0; jn < 8; jn++) {
                    float v0 = fmaxf(acc[im][jn][h * 2 + 0] + bcol[jn * 2 + 0], 0.f);
                    float v1 = fmaxf(acc[im][jn][h * 2 + 1] + bcol[jn * 2 + 1], 0.f);
                    *reinterpret_cast<__half2*>(drow + jn * 8 + cb) = __floats2half2_rn(v0, v1);
                }
            } else {
                const int   tok = g_idx[e * NB + slot];
                const float sc  = g_scale[e * NB + slot];
                float* yrow = y + (size_t)tok * NH + n0 + wn;
                #pragma unroll
                for (int jn = 0; jn < 8; jn++) {
                    atomicAdd(&yrow[jn * 8 + cb],     (acc[im][jn][h * 2 + 0] + bcol[jn * 2 + 0]) * sc);
                    atomicAdd(&yrow[jn * 8 + cb + 1], (acc[im][jn][h * 2 + 1] + bcol[jn * 2 + 1]) * sc);
                }
            }
        }
    }
}

// ---------------- aux loss ----------------
__global__ void aux_kernel(float* __restrict__ out) {
    float s = 0.f;
    #pragma unroll
    for (int e = 0; e < NE; e++)
        s += (g_psum[e] / (float)NB) * (g_rsum[e] / (float)NB);
    out[(size_t)NB * NH] = s * (float)NE;
}

// ---------------- launch ----------------
extern "C" void kernel_launch(void* const* d_in, const int* in_sizes, int n_in,
                              void* d_out, int out_size) {
    const float* x  = (const float*)d_in[0];
    const float* gw = (const float*)d_in[1];
    const float* gb = (const float*)d_in[2];
    const float* w1 = (const float*)d_in[3];
    const float* b1 = (const float*)d_in[4];
    const float* w2 = (const float*)d_in[5];
    const float* b2 = (const float*)d_in[6];
    float* y = (float*)d_out;

    const int SMEM_BYTES = 4 * 10240 + 4 * 16896;  // 108544
    cudaFuncSetAttribute(moe_gemm<NH, ND, false, 1>,
                         cudaFuncAttributeMaxDynamicSharedMemorySize, SMEM_BYTES);
    cudaFuncSetAttribute(moe_gemm<ND / 2, NH, true, 2>,
                         cudaFuncAttributeMaxDynamicSharedMemorySize, SMEM_BYTES);

    const size_t nx  = (size_t)NB * NH / 4;
    const size_t nw1 = (size_t)NE * NH * ND / 4;
    const size_t nw2 = (size_t)NE * ND * NH / 4;

    init_kernel<<<(NB * NH + 255) / 256, 256>>>(y);
    f2h_kernel<0><<<(unsigned)((nx  + 255) / 256), 256>>>(x,  nx);
    f2h_kernel<1><<<(unsigned)((nw1 + 255) / 256), 256>>>(w1, nw1);
    f2h_kernel<2><<<(unsigned)((nw2 + 255) / 256), 256>>>(w2, nw2);
    gate_kernel<<<NB, 256>>>(x, gw, gb);

    moe_gemm<NH, ND, false, 1><<<dim3(ND / 256, NB / 128, NE), 256, SMEM_BYTES>>>(b1, nullptr);
    moe_gemm<ND / 2, NH, true, 2><<<dim3(NH / 256, NB / 128, NE * 2), 256, SMEM_BYTES>>>(b2, y);
    aux_kernel<<<1, 1>>>(y);
}

// round 4
// speedup vs baseline: 1.1440x; 1.1440x over previous
#include <cuda_runtime.h>
#include <cuda_fp16.h>
#include <cstdint>

#define NB 4096   // tokens
#define NH 1024   // hidden
#define ND 4096   // expert dim
#define NE 8      // experts

// ---------------- scratch (__device__ globals: allocation-guard safe) ----------------
__device__ __half g_xh [(size_t)NB * NH];          //  8 MB  x fp16
__device__ __half g_w1h[(size_t)NE * NH * ND];     // 64 MB  w1 fp16 [e][h][d]
__device__ __half g_w2h[(size_t)NE * ND * NH];     // 64 MB  w2 fp16 [e][d][h]
__device__ __half g_h  [(size_t)NE * NB * ND];     // 256 MB h scratch
__device__ int    g_cnt[NE];
__device__ int    g_idx[NE * NB];
__device__ float  g_scale[NE * NB];
__device__ float  g_psum[NE];
__device__ float  g_rsum[NE];

// ---------------- helpers ----------------
__device__ __forceinline__ uint32_t smem_u32(const void* p) {
    return (uint32_t)__cvta_generic_to_shared(p);
}
__device__ __forceinline__ void cp16(uint32_t smem, const void* gmem) {
    asm volatile("cp.async.cg.shared.global [%0], [%1], 16;\n"
                 :: "r"(smem), "l"(gmem) : "memory");
}

// ---------------- prep 1: w1 fp32->fp16 + zero routing state (launch #1) ----------------
__global__ void prep_w1_kernel(const float* __restrict__ w1) {
    size_t i = (size_t)blockIdx.x * blockDim.x + threadIdx.x;
    if (i < (size_t)NE * NH * ND / 4) {
        float4 v = reinterpret_cast<const float4*>(w1)[i];
        __half2* d2 = reinterpret_cast<__half2*>(g_w1h) + i * 2;
        d2[0] = __floats2half2_rn(v.x, v.y);
        d2[1] = __floats2half2_rn(v.z, v.w);
    }
    if (i < NE) { g_cnt[i] = 0; g_psum[i] = 0.f; g_rsum[i] = 0.f; }
}

// ---------------- prep 2: w2 + x fp32->fp16, zero y (launch #2) ----------------
__global__ void prep_w2_kernel(const float* __restrict__ w2,
                               const float* __restrict__ x,
                               float* __restrict__ y) {
    size_t i = (size_t)blockIdx.x * blockDim.x + threadIdx.x;
    if (i < (size_t)NE * ND * NH / 4) {
        float4 v = reinterpret_cast<const float4*>(w2)[i];
        __half2* d2 = reinterpret_cast<__half2*>(g_w2h) + i * 2;
        d2[0] = __floats2half2_rn(v.x, v.y);
        d2[1] = __floats2half2_rn(v.z, v.w);
    }
    if (i < (size_t)NB * NH / 4) {
        float4 v = reinterpret_cast<const float4*>(x)[i];
        __half2* d2 = reinterpret_cast<__half2*>(g_xh) + i * 2;
        d2[0] = __floats2half2_rn(v.x, v.y);
        d2[1] = __floats2half2_rn(v.z, v.w);
        reinterpret_cast<float4*>(y)[i] = make_float4(0.f, 0.f, 0.f, 0.f);
    }
}

// ---------------- gating (launch #3) ----------------
__global__ void gate_kernel(const float* __restrict__ x,
                            const float* __restrict__ gw,
                            const float* __restrict__ gb) {
    __shared__ float sx[NH];
    __shared__ float slog[NE];
    const int b = blockIdx.x, tid = threadIdx.x;
    for (int i = tid; i < NH; i += 256) sx[i] = x[(size_t)b * NH + i];
    __syncthreads();
    const int w = tid >> 5, lane = tid & 31;
    float s = 0.f;
    for (int i = lane; i < NH; i += 32) s += sx[i] * gw[i * NE + w];
    #pragma unroll
    for (int o = 16; o; o >>= 1) s += __shfl_xor_sync(0xffffffffu, s, o);
    if (lane == 0) slog[w] = s + gb[w];
    __syncthreads();
    if (tid == 0) {
        float p[NE];
        float mx = slog[0];
        #pragma unroll
        for (int e = 1; e < NE; e++) mx = fmaxf(mx, slog[e]);
        float den = 0.f;
        #pragma unroll
        for (int e = 0; e < NE; e++) { p[e] = expf(slog[e] - mx); den += p[e]; }
        float inv = 1.f / den;
        #pragma unroll
        for (int e = 0; e < NE; e++) p[e] *= inv;
        int e1 = 0; float p1 = p[0];
        #pragma unroll
        for (int e = 1; e < NE; e++) if (p[e] > p1) { p1 = p[e]; e1 = e; }
        int e2 = (e1 == 0) ? 1 : 0; float p2 = p[e2];
        #pragma unroll
        for (int e = 0; e < NE; e++)
            if (e != e1 && p[e] > p2) { p2 = p[e]; e2 = e; }
        int pos = atomicAdd(&g_cnt[e1], 1);
        g_idx[e1 * NB + pos] = b; g_scale[e1 * NB + pos] = p1 * 0.5f;
        pos = atomicAdd(&g_cnt[e2], 1);
        g_idx[e2 * NB + pos] = b; g_scale[e2 * NB + pos] = p2 * 0.5f;
        #pragma unroll
        for (int e = 0; e < NE; e++) atomicAdd(&g_psum[e], p[e]);
        atomicAdd(&g_rsum[e1], 1.f);
        atomicAdd(&g_rsum[e2], 1.f);
    }
}

// ---------------- grouped GEMM: CTA 128x128, warp 32x64, 3-stage, 1 sync/chunk ----------------
// smem per stage: A 128 rows x 80B = 10240B, B 32 rows x 272B = 8704B; 3 stages = 56832B
// ISB==false: h = relu(Xg @ W1 + b1)    (KLEN=NH,   NDIM=ND, NSPLIT=1)
// ISB==true : y += scale*(h @ W2 + b2)  (KLEN=ND/2, NDIM=NH, NSPLIT=2, atomic, bias on split 0)
template<int KLEN, int NDIM, bool ISB, int NSPLIT>
__global__ void __launch_bounds__(256, 2)
moe_gemm(const float* __restrict__ bias, float* __restrict__ y) {
    constexpr int KT = KLEN / 32;
    constexpr int ASTG = 10240, BSTG = 8704;
    const int zi    = blockIdx.z;
    const int e     = (NSPLIT == 1) ? zi : (zi >> 1);
    const int split = (NSPLIT == 1) ? 0  : (zi & 1);
    const int cnt = g_cnt[e];
    const int m0  = blockIdx.y * 128;
    if (m0 >= cnt) return;
    const int n0    = blockIdx.x * 128;
    const int kbase = split * KLEN;
    const int tid   = threadIdx.x;

    extern __shared__ __align__(1024) char smem[];
    const uint32_t sA = smem_u32(smem);          // 3 * 10240
    const uint32_t sB = sA + 3 * ASTG;           // 3 * 8704

    // ---- gmem source pointers ----
    const int ar = tid >> 1;                      // A row (0..127), 2 threads/row
    const __half* Arow;
    if (ISB) {
        Arow = g_h + ((size_t)e * NB + m0 + ar) * ND + kbase;
    } else {
        const int s0  = m0 + ar;
        const int tok = g_idx[e * NB + (s0 < cnt ? s0 : 0)];
        Arow = g_xh + (size_t)tok * NH;
    }
    const __half* W = (ISB ? g_w2h : g_w1h)
                    + (size_t)e * (size_t)(KLEN * NSPLIT) * NDIM
                    + (size_t)kbase * NDIM + n0;
    const int br = tid >> 3;                      // B row (0..31), 8 threads/row

    auto load_stage = [&](int chunk, int s) {
        const uint32_t as = sA + s * ASTG + ar * 80;
        const __half* ag = Arow + chunk * 32;
        #pragma unroll
        for (int j = 0; j < 2; j++) {
            const int c4 = (tid & 1) * 2 + j;     // 16B col 0..3
            cp16(as + c4 * 16, ag + c4 * 8);
        }
        const uint32_t bs = sB + s * BSTG + br * 272;
        const __half* bg = W + (size_t)(chunk * 32 + br) * NDIM;
        #pragma unroll
        for (int j = 0; j < 2; j++) {
            const int cc = (tid & 7) * 2 + j;     // 16B col 0..15
            cp16(bs + cc * 16, bg + cc * 8);
        }
        asm volatile("cp.async.commit_group;" ::: "memory");
    };

    float acc[2][8][4];
    #pragma unroll
    for (int i = 0; i < 2; i++)
        #pragma unroll
        for (int j = 0; j < 8; j++)
            #pragma unroll
            for (int q = 0; q < 4; q++) acc[i][j][q] = 0.f;

    const int lane = tid & 31, warp = tid >> 5;
    const int wm = (warp & 3) * 32, wn = (warp >> 2) * 64;
    const uint32_t aoff = (uint32_t)(wm + (lane & 15)) * 80 + (lane >> 4) * 16;
    const uint32_t boff = (uint32_t)(lane & 15) * 272 + (uint32_t)(wn + (lane >> 4) * 8) * 2;

    load_stage(0, 0);
    load_stage(1, 1);

    for (int i = 0; i < KT; i++) {
        if (i < KT - 1) asm volatile("cp.async.wait_group 1;" ::: "memory");
        else            asm volatile("cp.async.wait_group 0;" ::: "memory");
        __syncthreads();
        if (i + 2 < KT) {
            int sp = i + 2; sp -= (sp / 3) * 3;
            load_stage(i + 2, sp);
        }
        int s = i; s -= (s / 3) * 3;
        const uint32_t ab = sA + s * ASTG + aoff;
        const uint32_t bb = sB + s * BSTG + boff;
        #pragma unroll
        for (int ks = 0; ks < 2; ks++) {
            uint32_t a[2][4], b[4][4];
            #pragma unroll
            for (int im = 0; im < 2; im++) {
                asm volatile("ldmatrix.sync.aligned.m8n8.x4.shared.b16 {%0,%1,%2,%3}, [%4];"
                             : "=r"(a[im][0]), "=r"(a[im][1]), "=r"(a[im][2]), "=r"(a[im][3])
                             : "r"(ab + im * 16 * 80 + ks * 32));
            }
            #pragma unroll
            for (int g = 0; g < 4; g++) {
                asm volatile("ldmatrix.sync.aligned.m8n8.x4.trans.shared.b16 {%0,%1,%2,%3}, [%4];"
                             : "=r"(b[g][0]), "=r"(b[g][1]), "=r"(b[g][2]), "=r"(b[g][3])
                             : "r"(bb + ks * 16 * 272 + g * 32));
            }
            #pragma unroll
            for (int im = 0; im < 2; im++)
                #pragma unroll
                for (int jn = 0; jn < 8; jn++) {
                    const uint32_t b0 = b[jn >> 1][(jn & 1) * 2 + 0];
                    const uint32_t b1 = b[jn >> 1][(jn & 1) * 2 + 1];
                    asm volatile("mma.sync.aligned.m16n8k16.row.col.f32.f16.f16.f32 "
                                 "{%0,%1,%2,%3},{%4,%5,%6,%7},{%8,%9},{%0,%1,%2,%3};"
                                 : "+f"(acc[im][jn][0]), "+f"(acc[im][jn][1]),
                                   "+f"(acc[im][jn][2]), "+f"(acc[im][jn][3])
                                 : "r"(a[im][0]), "r"(a[im][1]), "r"(a[im][2]), "r"(a[im][3]),
                                   "r"(b0), "r"(b1));
                }
        }
    }

    // ---- epilogue ----
    const int rb = lane >> 2;
    const int cb = (lane & 3) * 2;
    #pragma unroll
    for (int im = 0; im < 2; im++) {
        #pragma unroll
        for (int h = 0; h < 2; h++) {
            const int row  = wm + im * 16 + rb + h * 8;
            const int slot = m0 + row;
            if (slot >= cnt) continue;
            if (!ISB) {
                __half* drow = &g_h[((size_t)e * NB + slot) * ND + n0 + wn];
                #pragma unroll
                for (int jn = 0; jn < 8; jn++) {
                    const int gc = n0 + wn + jn * 8 + cb;
                    float v0 = fmaxf(acc[im][jn][h * 2 + 0] + bias[e * NDIM + gc],     0.f);
                    float v1 = fmaxf(acc[im][jn][h * 2 + 1] + bias[e * NDIM + gc + 1], 0.f);
                    *reinterpret_cast<__half2*>(drow + jn * 8 + cb) = __floats2half2_rn(v0, v1);
                }
            } else {
                const int   tok = g_idx[e * NB + slot];
                const float sc  = g_scale[e * NB + slot];
                float* yrow = y + (size_t)tok * NH + n0 + wn;
                #pragma unroll
                for (int jn = 0; jn < 8; jn++) {
                    const int gc = n0 + wn + jn * 8 + cb;
                    float bb0 = (split == 0) ? bias[e * NDIM + gc]     : 0.f;
                    float bb1 = (split == 0) ? bias[e * NDIM + gc + 1] : 0.f;
                    atomicAdd(&yrow[jn * 8 + cb],     (acc[im][jn][h * 2 + 0] + bb0) * sc);
                    atomicAdd(&yrow[jn * 8 + cb + 1], (acc[im][jn][h * 2 + 1] + bb1) * sc);
                }
            }
        }
    }
}

// ---------------- aux loss ----------------
__global__ void aux_kernel(float* __restrict__ out) {
    float s = 0.f;
    #pragma unroll
    for (int e = 0; e < NE; e++)
        s += (g_psum[e] / (float)NB) * (g_rsum[e] / (float)NB);
    out[(size_t)NB * NH] = s * (float)NE;
}

// ---------------- launch ----------------
extern "C" void kernel_launch(void* const* d_in, const int* in_sizes, int n_in,
                              void* d_out, int out_size) {
    const float* x  = (const float*)d_in[0];
    const float* gw = (const float*)d_in[1];
    const float* gb = (const float*)d_in[2];
    const float* w1 = (const float*)d_in[3];
    const float* b1 = (const float*)d_in[4];
    const float* w2 = (const float*)d_in[5];
    const float* b2 = (const float*)d_in[6];
    float* y = (float*)d_out;

    const int SMEM_BYTES = 3 * 10240 + 3 * 8704;   // 56832
    cudaFuncSetAttribute(moe_gemm<NH, ND, false, 1>,
                         cudaFuncAttributeMaxDynamicSharedMemorySize, SMEM_BYTES);
    cudaFuncSetAttribute(moe_gemm<ND / 2, NH, true, 2>,
                         cudaFuncAttributeMaxDynamicSharedMemorySize, SMEM_BYTES);

    const size_t nw = (size_t)NE * NH * ND / 4;    // 8M float4 groups

    prep_w1_kernel<<<(unsigned)((nw + 255) / 256), 256>>>(w1);            // #1
    prep_w2_kernel<<<(unsigned)((nw + 255) / 256), 256>>>(w2, x, y);      // #2
    gate_kernel<<<NB, 256>>>(x, gw, gb);                                  // #3
    moe_gemm<NH, ND, false, 1><<<dim3(ND / 128, NB / 128, NE), 256, SMEM_BYTES>>>(b1, nullptr);  // #4 (profiled)
    moe_gemm<ND / 2, NH, true, 2><<<dim3(NH / 128, NB / 128, NE * 2), 256, SMEM_BYTES>>>(b2, y); // #5
    aux_kernel<<<1, 1>>>(y);                                              // #6
}